// round 3
// baseline (speedup 1.0000x reference)
#include <cuda_runtime.h>

// QuaternionMaxAmpPool2d — round 3: 4 output pixels per thread, streaming
// loads/stores (__ldcs/__stcs), float4 stores.
//
// x: (bs, 256, 128, 128) fp32, c = comp*64 + cc. For each 2x2 window,
// amp[k] = sum_comp v[comp][k]^2 (sqrt monotone -> skipped); argmax k
// (first max, matches jnp.argmax); output the 4 component values at that k.
// out: (bs, 256, 64, 64).

__global__ void __launch_bounds__(256) qmax_pool_kernel(
    const float* __restrict__ x, float* __restrict__ out, int total_threads)
{
    int t = blockIdx.x * blockDim.x + threadIdx.x;
    if (t >= total_threads) return;

    // thread covers w2 in [4j, 4j+3]: 2 float4 per input row per comp
    int j  = t & 15;          // 0..15  (segment of 8 input floats)
    int h2 = (t >> 4) & 63;   // 0..63
    int cc = (t >> 10) & 63;  // 0..63
    int b  = t >> 16;

    const long long IN_B_STRIDE  = 256LL * 128 * 128;
    const long long COMP_STRIDE  = 64LL * 128 * 128;
    const long long PLANE_STRIDE = 128LL * 128;

    const float* base = x + (long long)b * IN_B_STRIDE
                          + (long long)cc * PLANE_STRIDE
                          + (long long)(h2 * 2) * 128
                          + (long long)j * 8;

    // r0[c][s], r1[c][s]: rows h0/h1, comp c, segment s (s=0: w 8j..8j+3)
    float4 r0[4][2], r1[4][2];
#pragma unroll
    for (int c = 0; c < 4; c++) {
        const float* p = base + (long long)c * COMP_STRIDE;
        r0[c][0] = __ldcs(reinterpret_cast<const float4*>(p));
        r0[c][1] = __ldcs(reinterpret_cast<const float4*>(p + 4));
        r1[c][0] = __ldcs(reinterpret_cast<const float4*>(p + 128));
        r1[c][1] = __ldcs(reinterpret_cast<const float4*>(p + 132));
    }

    // window k = kh*2 + kw: k0=(h0,w0) k1=(h0,w1) k2=(h1,w0) k3=(h1,w1)
    float4 result[4];  // result[c] holds the 4 output pixels for comp c

#pragma unroll
    for (int s = 0; s < 2; s++) {
        // pixel p0: input cols (0,1) of this segment; pixel p1: cols (2,3)
        float a0 = 0.f, a1 = 0.f, a2 = 0.f, a3 = 0.f;
        float b0 = 0.f, b1 = 0.f, b2 = 0.f, b3 = 0.f;
#pragma unroll
        for (int c = 0; c < 4; c++) {
            float4 u = r0[c][s], v = r1[c][s];
            a0 = fmaf(u.x, u.x, a0); a1 = fmaf(u.y, u.y, a1);
            a2 = fmaf(v.x, v.x, a2); a3 = fmaf(v.y, v.y, a3);
            b0 = fmaf(u.z, u.z, b0); b1 = fmaf(u.w, u.w, b1);
            b2 = fmaf(v.z, v.z, b2); b3 = fmaf(v.w, v.w, b3);
        }
        int k_lo = 0; float m = a0;
        if (a1 > m) { m = a1; k_lo = 1; }
        if (a2 > m) { m = a2; k_lo = 2; }
        if (a3 > m) { m = a3; k_lo = 3; }
        int k_hi = 0; float mh = b0;
        if (b1 > mh) { mh = b1; k_hi = 1; }
        if (b2 > mh) { mh = b2; k_hi = 2; }
        if (b3 > mh) { mh = b3; k_hi = 3; }

#pragma unroll
        for (int c = 0; c < 4; c++) {
            float4 u = r0[c][s], v = r1[c][s];
            float v_lo = (k_lo == 0) ? u.x : (k_lo == 1) ? u.y
                       : (k_lo == 2) ? v.x : v.y;
            float v_hi = (k_hi == 0) ? u.z : (k_hi == 1) ? u.w
                       : (k_hi == 2) ? v.z : v.w;
            if (s == 0) { result[c].x = v_lo; result[c].y = v_hi; }
            else        { result[c].z = v_lo; result[c].w = v_hi; }
        }
    }

    const long long OUT_B_STRIDE    = 256LL * 64 * 64;
    const long long OUT_C_STRIDE    = 64LL * 64;
    const long long OUT_COMP_STRIDE = 64LL * OUT_C_STRIDE;
    float* obase = out + (long long)b * OUT_B_STRIDE
                       + (long long)cc * OUT_C_STRIDE
                       + (long long)h2 * 64
                       + (long long)j * 4;

#pragma unroll
    for (int c = 0; c < 4; c++) {
        __stcs(reinterpret_cast<float4*>(obase + (long long)c * OUT_COMP_STRIDE),
               result[c]);
    }
}

extern "C" void kernel_launch(void* const* d_in, const int* in_sizes, int n_in,
                              void* d_out, int out_size)
{
    const float* x = (const float*)d_in[0];
    float* out = (float*)d_out;

    int bs = in_sizes[0] / (256 * 128 * 128);
    int total_threads = bs * 64 * 64 * 16;  // b * cc * h2 * 4-pixel segments

    int block = 256;
    int grid = (total_threads + block - 1) / block;
    qmax_pool_kernel<<<grid, block>>>(x, out, total_threads);
}

// round 5
// speedup vs baseline: 1.0400x; 1.0400x over previous
#include <cuda_runtime.h>

// QuaternionMaxAmpPool2d — round 5 (= R4 resubmit after infra failure):
// R2 mapping (2 output pixels/thread, float4 loads, float2 stores)
// + streaming cache hints (__ldcs/__stcs).
//
// x: (bs, 256, 128, 128) fp32, c = comp*64 + cc. For each 2x2 window,
// amp[k] = sum_comp v[comp][k]^2 (sqrt monotone -> skipped); argmax k
// (first max, matches jnp.argmax); output the 4 component values at that k.
// out: (bs, 256, 64, 64).

__global__ void __launch_bounds__(256) qmax_pool_kernel(
    const float* __restrict__ x, float* __restrict__ out, int total_threads)
{
    int t = blockIdx.x * blockDim.x + threadIdx.x;
    if (t >= total_threads) return;

    // decompose: j = w-pair (covers w2 = 2j, 2j+1), h2, cc, b
    int j  = t & 31;          // 0..31
    int h2 = (t >> 5) & 63;   // 0..63
    int cc = (t >> 11) & 63;  // 0..63
    int b  = t >> 17;

    const long long IN_B_STRIDE  = 256LL * 128 * 128;
    const long long COMP_STRIDE  = 64LL * 128 * 128;
    const long long PLANE_STRIDE = 128LL * 128;

    const float* base = x + (long long)b * IN_B_STRIDE
                          + (long long)cc * PLANE_STRIDE
                          + (long long)(h2 * 2) * 128
                          + (long long)j * 4;

    float4 r0[4], r1[4];
#pragma unroll
    for (int c = 0; c < 4; c++) {
        const float* p = base + (long long)c * COMP_STRIDE;
        r0[c] = __ldcs(reinterpret_cast<const float4*>(p));
        r1[c] = __ldcs(reinterpret_cast<const float4*>(p + 128));
    }

    // window k = kh*2 + kw: k0=(h0,w0) k1=(h0,w1) k2=(h1,w0) k3=(h1,w1)

    // ---- output pixel 0 (w2 = 2j): vals k0=r0.x k1=r0.y k2=r1.x k3=r1.y
    float a0 = 0.f, a1 = 0.f, a2 = 0.f, a3 = 0.f;
#pragma unroll
    for (int c = 0; c < 4; c++) {
        a0 = fmaf(r0[c].x, r0[c].x, a0);
        a1 = fmaf(r0[c].y, r0[c].y, a1);
        a2 = fmaf(r1[c].x, r1[c].x, a2);
        a3 = fmaf(r1[c].y, r1[c].y, a3);
    }
    int k_lo = 0; float m = a0;
    if (a1 > m) { m = a1; k_lo = 1; }
    if (a2 > m) { m = a2; k_lo = 2; }
    if (a3 > m) { m = a3; k_lo = 3; }

    // ---- output pixel 1 (w2 = 2j+1): k0=r0.z k1=r0.w k2=r1.z k3=r1.w
    float b0 = 0.f, b1 = 0.f, b2 = 0.f, b3 = 0.f;
#pragma unroll
    for (int c = 0; c < 4; c++) {
        b0 = fmaf(r0[c].z, r0[c].z, b0);
        b1 = fmaf(r0[c].w, r0[c].w, b1);
        b2 = fmaf(r1[c].z, r1[c].z, b2);
        b3 = fmaf(r1[c].w, r1[c].w, b3);
    }
    int k_hi = 0; float mh = b0;
    if (b1 > mh) { mh = b1; k_hi = 1; }
    if (b2 > mh) { mh = b2; k_hi = 2; }
    if (b3 > mh) { mh = b3; k_hi = 3; }

    const long long OUT_B_STRIDE    = 256LL * 64 * 64;
    const long long OUT_C_STRIDE    = 64LL * 64;
    const long long OUT_COMP_STRIDE = 64LL * OUT_C_STRIDE;
    float* obase = out + (long long)b * OUT_B_STRIDE
                       + (long long)cc * OUT_C_STRIDE
                       + (long long)h2 * 64
                       + (long long)j * 2;

#pragma unroll
    for (int c = 0; c < 4; c++) {
        float v_lo = (k_lo == 0) ? r0[c].x : (k_lo == 1) ? r0[c].y
                   : (k_lo == 2) ? r1[c].x : r1[c].y;
        float v_hi = (k_hi == 0) ? r0[c].z : (k_hi == 1) ? r0[c].w
                   : (k_hi == 2) ? r1[c].z : r1[c].w;
        __stcs(reinterpret_cast<float2*>(obase + (long long)c * OUT_COMP_STRIDE),
               make_float2(v_lo, v_hi));
    }
}

extern "C" void kernel_launch(void* const* d_in, const int* in_sizes, int n_in,
                              void* d_out, int out_size)
{
    const float* x = (const float*)d_in[0];
    float* out = (float*)d_out;

    int bs = in_sizes[0] / (256 * 128 * 128);
    int total_threads = bs * 64 * 64 * 32;  // b * cc * h2 * w-pairs

    int block = 256;
    int grid = (total_threads + block - 1) / block;
    qmax_pool_kernel<<<grid, block>>>(x, out, total_threads);
}